// round 2
// baseline (speedup 1.0000x reference)
#include <cuda_runtime.h>

#define BB 512
#define DD 512
#define INV_T (1.0f/0.07f)

// Scratch (no allocations allowed): sim matrix + global accumulators.
__device__ float  g_sim[BB * BB];
__device__ double g_loss;
__device__ double g_pair;
__device__ int    g_selmode;   // 0 = uint8 bool, 1 = int32, 2 = float32

__global__ void init_kernel() {
    g_loss = 0.0;
    g_pair = 0.0;
}

// Sniff mask_sents dtype from its first 512 bytes (in-bounds for u8/i32/f32).
// int32 0/1  -> words in {0,1}
// float 0/1  -> words in {0, 0x3F800000}
// uint8 bool -> words pack 4 random 0/1 bytes; cannot match the above for all 128 words.
__global__ void detect_kernel(const unsigned int* __restrict__ w) {
    int t = threadIdx.x;           // 128 threads
    unsigned v = w[t];
    bool i32ok = (v == 0u) || (v == 1u);
    bool f32ok = (v == 0u) || (v == 0x3F800000u);
    int c1 = __syncthreads_count(i32ok);
    int c2 = __syncthreads_count(f32ok);
    if (t == 0) g_selmode = (c1 == 128) ? 1 : ((c2 == 128) ? 2 : 0);
}

// sim = (A @ A^T) / T, A = features[:,0,:] (contiguous 512x512 fp32).
// 64x64 block tile, 16x16 threads, 4x4 micro-tile per thread, K-chunks of 16.
__global__ __launch_bounds__(256) void gemm_sim_kernel(const float* __restrict__ A) {
    __shared__ float As[16][68];   // stride 68 floats: 16B-aligned rows, <=2-way STS conflicts
    __shared__ float Bs[16][68];
    const int tx = threadIdx.x, ty = threadIdx.y;
    const int tid = ty * 16 + tx;
    const int rowBase = blockIdx.y * 64;
    const int colBase = blockIdx.x * 64;

    float acc[4][4];
#pragma unroll
    for (int i = 0; i < 4; i++)
#pragma unroll
        for (int j = 0; j < 4; j++) acc[i][j] = 0.f;

    for (int kb = 0; kb < DD; kb += 16) {
#pragma unroll
        for (int l = 0; l < 4; l++) {
            int idx = tid + l * 256;          // 0..1023
            int r = idx >> 4;                 // 0..63
            int k = idx & 15;                 // 0..15
            As[k][r] = A[(rowBase + r) * DD + kb + k];
            Bs[k][r] = A[(colBase + r) * DD + kb + k];
        }
        __syncthreads();
#pragma unroll
        for (int k = 0; k < 16; k++) {
            float4 a = *(const float4*)&As[k][ty * 4];
            float4 b = *(const float4*)&Bs[k][tx * 4];
            acc[0][0] += a.x * b.x; acc[0][1] += a.x * b.y; acc[0][2] += a.x * b.z; acc[0][3] += a.x * b.w;
            acc[1][0] += a.y * b.x; acc[1][1] += a.y * b.y; acc[1][2] += a.y * b.z; acc[1][3] += a.y * b.w;
            acc[2][0] += a.z * b.x; acc[2][1] += a.z * b.y; acc[2][2] += a.z * b.z; acc[2][3] += a.z * b.w;
            acc[3][0] += a.w * b.x; acc[3][1] += a.w * b.y; acc[3][2] += a.w * b.z; acc[3][3] += a.w * b.w;
        }
        __syncthreads();
    }

#pragma unroll
    for (int i = 0; i < 4; i++) {
        int row = rowBase + ty * 4 + i;
#pragma unroll
        for (int j = 0; j < 4; j++)
            g_sim[row * BB + colBase + tx * 4 + j] = acc[i][j] * INV_T;
    }
}

// -log_sigmoid(x) = softplus(-x); stable: max(x,0) + log(1+exp(-|x|))
__device__ __forceinline__ float softplus_f(float x) {
    return fmaxf(x, 0.f) + __logf(1.f + __expf(-fabsf(x)));
}

// One block per row i. Compact positive/negative sim values into shared, then
// dense cP x cN pair loop (each thread owns strided p's, streams all n's).
__global__ __launch_bounds__(256) void pair_loss_kernel(
    const float* __restrict__ mask,
    const void* __restrict__ sel_raw)
{
    const int i = blockIdx.x;

    const int mode = g_selmode;
    bool active;
    if (mode == 1)      active = ((const int*)sel_raw)[i] != 0;
    else if (mode == 2) active = ((const float*)sel_raw)[i] != 0.f;
    else                active = ((const unsigned char*)sel_raw)[i] != 0;
    if (!active) return;   // sel gates both mask_pos and mask_neg -> zero contribution

    __shared__ float sPos[BB];
    __shared__ float sNeg[BB];
    __shared__ int   cnt[2];
    __shared__ float red[8];

    const int tid = threadIdx.x;
    if (tid < 2) cnt[tid] = 0;
    __syncthreads();

    const float* mrow = mask + (size_t)i * BB;
    const float* srow = g_sim + (size_t)i * BB;

    for (int j = tid; j < BB; j += 256) {
        if (j == i) continue;                 // logits_mask removes the diagonal
        float s = srow[j];
        if (mrow[j] != 0.f) sPos[atomicAdd(&cnt[0], 1)] = s;
        else                sNeg[atomicAdd(&cnt[1], 1)] = s;
    }
    __syncthreads();

    const int cP = cnt[0];
    const int cN = cnt[1];

    float local = 0.f;
    for (int p = tid; p < cP; p += 256) {
        float sp = sPos[p];
        float a0 = 0.f, a1 = 0.f, a2 = 0.f, a3 = 0.f;
        int n = 0;
        for (; n + 4 <= cN; n += 4) {
            float x0 = sNeg[n + 0] - sp;
            float x1 = sNeg[n + 1] - sp;
            float x2 = sNeg[n + 2] - sp;
            float x3 = sNeg[n + 3] - sp;
            a0 += softplus_f(x0);
            a1 += softplus_f(x1);
            a2 += softplus_f(x2);
            a3 += softplus_f(x3);
        }
        for (; n < cN; n++) a0 += softplus_f(sNeg[n] - sp);
        local += (a0 + a1) + (a2 + a3);
    }

    // block reduce
#pragma unroll
    for (int o = 16; o > 0; o >>= 1)
        local += __shfl_xor_sync(0xffffffff, local, o);
    if ((tid & 31) == 0) red[tid >> 5] = local;
    __syncthreads();
    if (tid == 0) {
        float bs = 0.f;
#pragma unroll
        for (int w = 0; w < 8; w++) bs += red[w];
        atomicAdd(&g_loss, (double)bs);
        atomicAdd(&g_pair, (double)cP * (double)cN);
    }
}

__global__ void finalize_kernel(float* __restrict__ out) {
    double pn = g_pair;
    double ls = g_loss;
    double r = (pn > 0.0) ? (ls / fmax(pn, 1.0)) : ls;
    out[0] = (float)r;
}

extern "C" void kernel_launch(void* const* d_in, const int* in_sizes, int n_in,
                              void* d_out, int out_size) {
    const float* features = (const float*)d_in[0];   // (512,1,512) fp32
    const float* mask     = (const float*)d_in[1];   // (512,512)   fp32
    const void*  sel      = d_in[2];                 // (512,) bool -> dtype sniffed

    init_kernel<<<1, 1>>>();
    detect_kernel<<<1, 128>>>((const unsigned int*)sel);
    dim3 gridG(8, 8), blkG(16, 16);
    gemm_sim_kernel<<<gridG, blkG>>>(features);
    pair_loss_kernel<<<BB, 256>>>(mask, sel);
    finalize_kernel<<<1, 1>>>((float*)d_out);
}

// round 7
// speedup vs baseline: 2.4942x; 2.4942x over previous
#include <cuda_runtime.h>

#define BB 512
#define DD 512
#define INV_T (1.0f/0.07f)
#define NSLICE 4
#define SLICE_W (BB / NSLICE)   // 128 columns of j per slice

__device__ float  g_sim[BB * BB];
__device__ double g_loss;
__device__ double g_pair;
__device__ int    g_selmode;   // 0 = uint8 bool, 1 = int32, 2 = float32

// Zero accumulators + sniff mask_sents dtype from its first 512 bytes.
// int32 0/1 -> words in {0,1}; float 0/1 -> {0,0x3F800000};
// uint8 bool -> 4 random 0/1 bytes per word (can't match the others for all 128 words).
__global__ void init_detect_kernel(const unsigned int* __restrict__ w) {
    int t = threadIdx.x;           // 128 threads
    unsigned v = w[t];
    bool i32ok = (v == 0u) || (v == 1u);
    bool f32ok = (v == 0u) || (v == 0x3F800000u);
    int c1 = __syncthreads_count(i32ok);
    int c2 = __syncthreads_count(f32ok);
    if (t == 0) {
        g_selmode = (c1 == 128) ? 1 : ((c2 == 128) ? 2 : 0);
        g_loss = 0.0;
        g_pair = 0.0;
    }
}

// sim = (A @ A^T) / T.  32x32 tile -> 256 blocks (2 waves on 148 SMs),
// 16x16 threads, 2x2 micro-tile, K-chunk 32.  Row stride 34 (even) keeps
// every float2 smem load 8B-aligned (the R3 trap).
__global__ __launch_bounds__(256) void gemm_sim_kernel(const float* __restrict__ A) {
    __shared__ __align__(16) float As[32][34];
    __shared__ __align__(16) float Bs[32][34];
    const int tx = threadIdx.x, ty = threadIdx.y;
    const int tid = ty * 16 + tx;
    const int rowBase = blockIdx.y * 32;
    const int colBase = blockIdx.x * 32;

    const int lr = tid >> 3;          // 0..31 row within tile
    const int lk = (tid & 7) * 4;     // 0,4,...,28

    float acc00 = 0.f, acc01 = 0.f, acc10 = 0.f, acc11 = 0.f;

    for (int kb = 0; kb < DD; kb += 32) {
        float4 a4 = *(const float4*)&A[(rowBase + lr) * DD + kb + lk];
        float4 b4 = *(const float4*)&A[(colBase + lr) * DD + kb + lk];
        As[lk + 0][lr] = a4.x; As[lk + 1][lr] = a4.y; As[lk + 2][lr] = a4.z; As[lk + 3][lr] = a4.w;
        Bs[lk + 0][lr] = b4.x; Bs[lk + 1][lr] = b4.y; Bs[lk + 2][lr] = b4.z; Bs[lk + 3][lr] = b4.w;
        __syncthreads();
#pragma unroll
        for (int k = 0; k < 32; k++) {
            float2 a = *(const float2*)&As[k][ty * 2];   // broadcast across half-warp
            float2 b = *(const float2*)&Bs[k][tx * 2];   // banks {2tx,2tx+1}
            acc00 += a.x * b.x; acc01 += a.x * b.y;
            acc10 += a.y * b.x; acc11 += a.y * b.y;
        }
        __syncthreads();
    }

    int row = rowBase + ty * 2;
    int col = colBase + tx * 2;
    g_sim[row * BB + col]           = acc00 * INV_T;
    g_sim[row * BB + col + 1]       = acc01 * INV_T;
    g_sim[(row + 1) * BB + col]     = acc10 * INV_T;
    g_sim[(row + 1) * BB + col + 1] = acc11 * INV_T;
}

// Exact stable softplus (R2-proven): max(x,0) + log(1+e^{-|x|}).  2 MUFU.
__device__ __forceinline__ float softplus_f(float x) {
    return fmaxf(x, 0.f) + __logf(1.f + __expf(-fabsf(x)));
}

// Pair loss.  Block (i, slice): positives compacted from the FULL row,
// negatives compacted only from j in [slice*128, slice*128+128).
// Processed pair-set = {all pos} x {neg j in slice}: disjoint + complete
// across slices REGARDLESS of compaction order -> deterministic by
// construction (the R4-R6 race sliced per-block permutations instead).
__global__ __launch_bounds__(256) void pair_loss_kernel(
    const float* __restrict__ mask,
    const void* __restrict__ sel_raw)
{
    const int i     = blockIdx.x;
    const int slice = blockIdx.y;

    const int mode = g_selmode;
    bool active;
    if (mode == 1)      active = ((const int*)sel_raw)[i] != 0;
    else if (mode == 2) active = ((const float*)sel_raw)[i] != 0.f;
    else                active = ((const unsigned char*)sel_raw)[i] != 0;
    if (!active) return;

    __shared__ float sPos[BB];
    __shared__ float sNeg[SLICE_W];
    __shared__ int   cnt[2];
    __shared__ float red[8];

    const int tid = threadIdx.x;
    if (tid < 2) cnt[tid] = 0;
    __syncthreads();

    const float* mrow = mask + (size_t)i * BB;
    const float* srow = g_sim + (size_t)i * BB;
    const int jLo = slice * SLICE_W;
    const int jHi = jLo + SLICE_W;

    // Positives: full row.  Negatives: only this block's j-slice.
    for (int j = tid; j < BB; j += 256) {
        if (j == i) continue;                 // diagonal excluded from both
        if (mrow[j] != 0.f) {
            sPos[atomicAdd(&cnt[0], 1)] = srow[j];
        } else if (j >= jLo && j < jHi) {
            sNeg[atomicAdd(&cnt[1], 1)] = srow[j];
        }
    }
    __syncthreads();

    const int cP    = cnt[0];
    const int cNloc = cnt[1];

    float local = 0.f;
    for (int p = tid; p < cP; p += 256) {
        float sp = sPos[p];
        float a0 = 0.f, a1 = 0.f, a2 = 0.f, a3 = 0.f;
        int n = 0;
        for (; n + 4 <= cNloc; n += 4) {
            a0 += softplus_f(sNeg[n + 0] - sp);
            a1 += softplus_f(sNeg[n + 1] - sp);
            a2 += softplus_f(sNeg[n + 2] - sp);
            a3 += softplus_f(sNeg[n + 3] - sp);
        }
        for (; n < cNloc; n++) a0 += softplus_f(sNeg[n] - sp);
        local += (a0 + a1) + (a2 + a3);
    }

#pragma unroll
    for (int o = 16; o > 0; o >>= 1)
        local += __shfl_xor_sync(0xffffffff, local, o);
    if ((tid & 31) == 0) red[tid >> 5] = local;
    __syncthreads();
    if (tid == 0) {
        float bs = 0.f;
#pragma unroll
        for (int w = 0; w < 8; w++) bs += red[w];
        atomicAdd(&g_loss, (double)bs);
        // pair_num per row = cP * (511 - cP); deterministic closed form.
        if (slice == 0) atomicAdd(&g_pair, (double)cP * (double)(BB - 1 - cP));
    }
}

__global__ void finalize_kernel(float* __restrict__ out) {
    double pn = g_pair;
    double ls = g_loss;
    double r = (pn > 0.0) ? (ls / fmax(pn, 1.0)) : ls;
    out[0] = (float)r;
}

extern "C" void kernel_launch(void* const* d_in, const int* in_sizes, int n_in,
                              void* d_out, int out_size) {
    const float* features = (const float*)d_in[0];   // (512,1,512) fp32
    const float* mask     = (const float*)d_in[1];   // (512,512)   fp32
    const void*  sel      = d_in[2];                 // (512,) bool -> dtype sniffed

    init_detect_kernel<<<1, 128>>>((const unsigned int*)sel);
    dim3 gridG(16, 16), blkG(16, 16);
    gemm_sim_kernel<<<gridG, blkG>>>(features);
    pair_loss_kernel<<<dim3(BB, NSLICE), 256>>>(mask, sel);
    finalize_kernel<<<1, 1>>>((float*)d_out);
}